// round 1
// baseline (speedup 1.0000x reference)
#include <cuda_runtime.h>
#include <math.h>

#define D_MODEL 512
#define N_HEADS 8
#define DK      64
#define BATCH   4
#define SEQ     2048
#define BT      (BATCH * SEQ)   // 8192
#define LN_EPS  1e-5f

// ---------------- scratch (device globals; no allocation allowed) ----------
__device__ float g_normed[BT * D_MODEL];
__device__ float g_q[BT * D_MODEL];      // [b][h][t][dk]
__device__ float g_k[BT * D_MODEL];      // [b][h][t][dk] (PE already added)
__device__ float g_v[BT * D_MODEL];      // [b][h][t][dk]
__device__ float g_ctx[BT * D_MODEL];    // [b][t][h*dk]  (row-major B*T x D)

// ---------------- sinusoidal relative PE -----------------------------------
__device__ __forceinline__ float pe_val(int t, int d) {
    int p = d >> 1;
    float div = expf(-(logf(10000.0f) / (float)DK) * (float)(2 * p));
    float ang = (float)t * div;
    return (d & 1) ? cosf(ang) : sinf(ang);
}

// ---------------- LayerNorm -------------------------------------------------
__global__ void ln_kernel(const float* __restrict__ x,
                          const float* __restrict__ gamma,
                          const float* __restrict__ beta) {
    int row = blockIdx.x;
    int tid = threadIdx.x;            // 256 threads
    const float* xr = x + (size_t)row * D_MODEL;
    float v0 = xr[tid];
    float v1 = xr[tid + 256];
    float s  = v0 + v1;
    float sq = v0 * v0 + v1 * v1;
    #pragma unroll
    for (int o = 16; o > 0; o >>= 1) {
        s  += __shfl_xor_sync(0xffffffffu, s,  o);
        sq += __shfl_xor_sync(0xffffffffu, sq, o);
    }
    __shared__ float ss[8], ssq[8];
    __shared__ float s_mu, s_rstd;
    int w = tid >> 5, l = tid & 31;
    if (l == 0) { ss[w] = s; ssq[w] = sq; }
    __syncthreads();
    if (tid == 0) {
        float S = 0.f, SQ = 0.f;
        #pragma unroll
        for (int i = 0; i < 8; i++) { S += ss[i]; SQ += ssq[i]; }
        float mu = S * (1.0f / D_MODEL);
        float var = SQ * (1.0f / D_MODEL) - mu * mu;
        s_mu = mu;
        s_rstd = rsqrtf(var + LN_EPS);
    }
    __syncthreads();
    float mu = s_mu, rs = s_rstd;
    float* out = g_normed + (size_t)row * D_MODEL;
    out[tid]       = (v0 - mu) * rs * gamma[tid]       + beta[tid];
    out[tid + 256] = (v1 - mu) * rs * gamma[tid + 256] + beta[tid + 256];
}

// ---------------- fused QKV GEMM (+bias, +PE on K, scatter to heads) --------
// C[m][n] = sum_k normed[m][k] * W[n][k],  M=8192, N=512 per weight, K=512
// blockDim 256, BM=BN=64, BK=16, 4x4 per thread.
__global__ void qkv_kernel(const float* __restrict__ wq, const float* __restrict__ bq,
                           const float* __restrict__ wk, const float* __restrict__ bk,
                           const float* __restrict__ wv, const float* __restrict__ bv) {
    __shared__ float As[16][64];
    __shared__ float Ws[16][64];
    int tid = threadIdx.x;
    int tx = tid & 15, ty = tid >> 4;
    int m0 = blockIdx.x * 64;
    int by = blockIdx.y;                // 0..23
    int wsel = by >> 3;                 // 0=Q 1=K 2=V
    int n0 = (by & 7) * 64;
    const float* W    = (wsel == 0) ? wq : (wsel == 1) ? wk : wv;
    const float* bias = (wsel == 0) ? bq : (wsel == 1) ? bk : bv;

    int lrow = tid >> 2;   // 0..63
    int lseg = tid & 3;    // 0..3
    const float* Ap = g_normed + (size_t)(m0 + lrow) * D_MODEL + lseg * 4;
    const float* Wp = W        + (size_t)(n0 + lrow) * D_MODEL + lseg * 4;

    float acc[4][4] = {};
    for (int k0 = 0; k0 < D_MODEL; k0 += 16) {
        float4 a4 = *(const float4*)(Ap + k0);
        float4 w4 = *(const float4*)(Wp + k0);
        As[lseg * 4 + 0][lrow] = a4.x; As[lseg * 4 + 1][lrow] = a4.y;
        As[lseg * 4 + 2][lrow] = a4.z; As[lseg * 4 + 3][lrow] = a4.w;
        Ws[lseg * 4 + 0][lrow] = w4.x; Ws[lseg * 4 + 1][lrow] = w4.y;
        Ws[lseg * 4 + 2][lrow] = w4.z; Ws[lseg * 4 + 3][lrow] = w4.w;
        __syncthreads();
        #pragma unroll
        for (int k = 0; k < 16; k++) {
            float a[4], b[4];
            #pragma unroll
            for (int i = 0; i < 4; i++) { a[i] = As[k][ty * 4 + i]; b[i] = Ws[k][tx * 4 + i]; }
            #pragma unroll
            for (int i = 0; i < 4; i++)
                #pragma unroll
                for (int j = 0; j < 4; j++)
                    acc[i][j] += a[i] * b[j];
        }
        __syncthreads();
    }

    float* dst = (wsel == 0) ? g_q : (wsel == 1) ? g_k : g_v;
    #pragma unroll
    for (int i = 0; i < 4; i++) {
        int m = m0 + ty * 4 + i;
        int bidx = m >> 11;            // /2048
        int t = m & (SEQ - 1);
        #pragma unroll
        for (int j = 0; j < 4; j++) {
            int n = n0 + tx * 4 + j;
            int h = n >> 6, d = n & 63;
            float v = acc[i][j] + bias[n];
            if (wsel == 1) v += pe_val(t, d);
            dst[(((size_t)bidx * N_HEADS + h) * SEQ + t) * DK + d] = v;
        }
    }
}

// ---------------- flash attention (fp32) ------------------------------------
// grid (32 qtiles, 8 heads, 4 batch), 256 threads (16x16), 4x4 per thread.
__global__ void attn_kernel() {
    extern __shared__ float smem[];
    float (*Qs)[65] = (float(*)[65])(smem);
    float (*Ks)[65] = (float(*)[65])(smem + 64 * 65);
    float (*Vs)[65] = (float(*)[65])(smem + 2 * 64 * 65);
    float (*Ps)[65] = (float(*)[65])(smem + 3 * 64 * 65);

    int tid = threadIdx.x;
    int tx = tid & 15, ty = tid >> 4;
    int bh = blockIdx.z * N_HEADS + blockIdx.y;
    int q0 = blockIdx.x * 64;
    const float* Qb = g_q + (size_t)bh * SEQ * DK;
    const float* Kb = g_k + (size_t)bh * SEQ * DK;
    const float* Vb = g_v + (size_t)bh * SEQ * DK;

    // load Q tile (64x64)
    #pragma unroll
    for (int it = 0; it < 4; it++) {
        int idx = tid + it * 256;       // float4 index, 0..1023
        int r = idx >> 4;
        int c = (idx & 15) * 4;
        float4 v = *(const float4*)&Qb[(size_t)(q0 + r) * DK + c];
        Qs[r][c] = v.x; Qs[r][c + 1] = v.y; Qs[r][c + 2] = v.z; Qs[r][c + 3] = v.w;
    }

    float mrow[4] = {-1e30f, -1e30f, -1e30f, -1e30f};
    float lrow[4] = {0.f, 0.f, 0.f, 0.f};
    float O[4][4] = {};

    for (int s0 = 0; s0 < SEQ; s0 += 64) {
        __syncthreads();   // Ks/Vs reuse + Qs visibility (first iter)
        #pragma unroll
        for (int it = 0; it < 4; it++) {
            int idx = tid + it * 256;
            int r = idx >> 4;
            int c = (idx & 15) * 4;
            float4 kv = *(const float4*)&Kb[(size_t)(s0 + r) * DK + c];
            Ks[r][c] = kv.x; Ks[r][c + 1] = kv.y; Ks[r][c + 2] = kv.z; Ks[r][c + 3] = kv.w;
            float4 vv = *(const float4*)&Vb[(size_t)(s0 + r) * DK + c];
            Vs[r][c] = vv.x; Vs[r][c + 1] = vv.y; Vs[r][c + 2] = vv.z; Vs[r][c + 3] = vv.w;
        }
        __syncthreads();

        float S[4][4] = {};
        #pragma unroll 16
        for (int d = 0; d < 64; d++) {
            float a[4], b[4];
            #pragma unroll
            for (int i = 0; i < 4; i++) { a[i] = Qs[ty * 4 + i][d]; b[i] = Ks[tx * 4 + i][d]; }
            #pragma unroll
            for (int i = 0; i < 4; i++)
                #pragma unroll
                for (int j = 0; j < 4; j++)
                    S[i][j] += a[i] * b[j];
        }
        #pragma unroll
        for (int i = 0; i < 4; i++)
            #pragma unroll
            for (int j = 0; j < 4; j++)
                S[i][j] *= 0.125f;      // 1/sqrt(64)

        // row max over 4 local cols + 16 lanes
        #pragma unroll
        for (int i = 0; i < 4; i++) {
            float rm = fmaxf(fmaxf(S[i][0], S[i][1]), fmaxf(S[i][2], S[i][3]));
            #pragma unroll
            for (int o = 1; o < 16; o <<= 1)
                rm = fmaxf(rm, __shfl_xor_sync(0xffffffffu, rm, o));
            float mnew = fmaxf(mrow[i], rm);
            float alpha = __expf(mrow[i] - mnew);
            float rs = 0.f;
            #pragma unroll
            for (int j = 0; j < 4; j++) {
                S[i][j] = __expf(S[i][j] - mnew);
                rs += S[i][j];
            }
            #pragma unroll
            for (int o = 1; o < 16; o <<= 1)
                rs += __shfl_xor_sync(0xffffffffu, rs, o);
            lrow[i] = lrow[i] * alpha + rs;
            mrow[i] = mnew;
            #pragma unroll
            for (int j = 0; j < 4; j++) {
                O[i][j] *= alpha;
                Ps[ty * 4 + i][tx * 4 + j] = S[i][j];
            }
        }
        __syncthreads();

        #pragma unroll 16
        for (int s = 0; s < 64; s++) {
            float p[4], v[4];
            #pragma unroll
            for (int i = 0; i < 4; i++) { p[i] = Ps[ty * 4 + i][s]; v[i] = Vs[s][tx * 4 + i]; }
            #pragma unroll
            for (int i = 0; i < 4; i++)
                #pragma unroll
                for (int j = 0; j < 4; j++)
                    O[i][j] += p[i] * v[j];
        }
    }

    int bidx = blockIdx.z, h = blockIdx.y;
    #pragma unroll
    for (int i = 0; i < 4; i++) {
        int t = q0 + ty * 4 + i;
        float inv = 1.0f / lrow[i];
        #pragma unroll
        for (int j = 0; j < 4; j++) {
            int d = tx * 4 + j;
            g_ctx[((size_t)bidx * SEQ + t) * D_MODEL + h * DK + d] = O[i][j] * inv;
        }
    }
}

// ---------------- output projection -----------------------------------------
__global__ void out_kernel(const float* __restrict__ wo, const float* __restrict__ bo,
                           float* __restrict__ out) {
    __shared__ float As[16][64];
    __shared__ float Ws[16][64];
    int tid = threadIdx.x;
    int tx = tid & 15, ty = tid >> 4;
    int m0 = blockIdx.x * 64;
    int n0 = blockIdx.y * 64;

    int lrow = tid >> 2;
    int lseg = tid & 3;
    const float* Ap = g_ctx + (size_t)(m0 + lrow) * D_MODEL + lseg * 4;
    const float* Wp = wo    + (size_t)(n0 + lrow) * D_MODEL + lseg * 4;

    float acc[4][4] = {};
    for (int k0 = 0; k0 < D_MODEL; k0 += 16) {
        float4 a4 = *(const float4*)(Ap + k0);
        float4 w4 = *(const float4*)(Wp + k0);
        As[lseg * 4 + 0][lrow] = a4.x; As[lseg * 4 + 1][lrow] = a4.y;
        As[lseg * 4 + 2][lrow] = a4.z; As[lseg * 4 + 3][lrow] = a4.w;
        Ws[lseg * 4 + 0][lrow] = w4.x; Ws[lseg * 4 + 1][lrow] = w4.y;
        Ws[lseg * 4 + 2][lrow] = w4.z; Ws[lseg * 4 + 3][lrow] = w4.w;
        __syncthreads();
        #pragma unroll
        for (int k = 0; k < 16; k++) {
            float a[4], b[4];
            #pragma unroll
            for (int i = 0; i < 4; i++) { a[i] = As[k][ty * 4 + i]; b[i] = Ws[k][tx * 4 + i]; }
            #pragma unroll
            for (int i = 0; i < 4; i++)
                #pragma unroll
                for (int j = 0; j < 4; j++)
                    acc[i][j] += a[i] * b[j];
        }
        __syncthreads();
    }
    #pragma unroll
    for (int i = 0; i < 4; i++) {
        int m = m0 + ty * 4 + i;
        #pragma unroll
        for (int j = 0; j < 4; j++) {
            int n = n0 + tx * 4 + j;
            out[(size_t)m * D_MODEL + n] = acc[i][j] + bo[n];
        }
    }
}

// ---------------- launch -----------------------------------------------------
extern "C" void kernel_launch(void* const* d_in, const int* in_sizes, int n_in,
                              void* d_out, int out_size) {
    const float* x    = (const float*)d_in[0];
    const float* ln_g = (const float*)d_in[1];
    const float* ln_b = (const float*)d_in[2];
    const float* wq   = (const float*)d_in[3];
    const float* bq   = (const float*)d_in[4];
    const float* wk   = (const float*)d_in[5];
    const float* bk   = (const float*)d_in[6];
    const float* wv   = (const float*)d_in[7];
    const float* bv   = (const float*)d_in[8];
    const float* wo   = (const float*)d_in[9];
    const float* bo   = (const float*)d_in[10];

    ln_kernel<<<BT, 256>>>(x, ln_g, ln_b);
    qkv_kernel<<<dim3(128, 24), 256>>>(wq, bq, wk, bk, wv, bv);

    const int ATTN_SMEM = 4 * 64 * 65 * (int)sizeof(float);   // 66560 B
    cudaFuncSetAttribute(attn_kernel, cudaFuncAttributeMaxDynamicSharedMemorySize, ATTN_SMEM);
    attn_kernel<<<dim3(32, 8, 4), 256, ATTN_SMEM>>>();

    out_kernel<<<dim3(128, 8), 256>>>(wo, bo, (float*)d_out);
}

// round 4
// speedup vs baseline: 3.5157x; 3.5157x over previous
#include <cuda_runtime.h>
#include <cstdint>
#include <math.h>

#define D_MODEL 512
#define N_HEADS 8
#define DK      64
#define BATCH   4
#define SEQ     2048
#define BT      (BATCH * SEQ)   // 8192
#define LN_EPS  1e-5f
#define PE_C    0.14391157f     // ln(10000)/64

// ---------------- scratch (device globals; no allocation allowed) -----------
__device__ float g_normed[BT * D_MODEL];   // tf32-rounded LN output
__device__ float g_q[BT * D_MODEL];        // [b][h][t][dk], tf32-rounded
__device__ float g_k[BT * D_MODEL];        // [b][h][t][dk], +PE, tf32-rounded
__device__ float g_vt[BT * D_MODEL];       // [b][h][dk][t], tf32-rounded
__device__ float g_ctx[BT * D_MODEL];      // [b][t][h*dk], tf32-rounded
__device__ float g_wr[4 * D_MODEL * D_MODEL];  // rounded wq,wk,wv,wo

// ---------------- PTX helpers ------------------------------------------------
__device__ __forceinline__ uint32_t smem_u32(const void* p) {
    return (uint32_t)__cvta_generic_to_shared((void*)p);
}
__device__ __forceinline__ uint32_t f2tf(float x) {
    uint32_t r; asm("cvt.rna.tf32.f32 %0, %1;" : "=r"(r) : "f"(x)); return r;
}
__device__ __forceinline__ float f2tff(float x) { return __uint_as_float(f2tf(x)); }

#define CP16(dst, src) \
    asm volatile("cp.async.cg.shared.global [%0], [%1], 16;" :: "r"(dst), "l"(src))
#define CP_COMMIT() asm volatile("cp.async.commit_group;" ::: "memory")
#define CP_WAIT1()  asm volatile("cp.async.wait_group 1;" ::: "memory")
#define CP_WAIT0()  asm volatile("cp.async.wait_group 0;" ::: "memory")

#define LDSM4(r0, r1, r2, r3, addr) \
    asm volatile("ldmatrix.sync.aligned.m8n8.x4.shared.b16 {%0,%1,%2,%3}, [%4];" \
        : "=r"(r0), "=r"(r1), "=r"(r2), "=r"(r3) : "r"(addr))

#define STS64(addr, a, b) \
    asm volatile("st.shared.v2.b32 [%0], {%1,%2};" :: "r"(addr), "r"(a), "r"(b))

// C (f32x4) += A(tf32 m16k8) * B(tf32 k8n8)
#define MMA_TF32(c, a, b) \
    asm volatile("mma.sync.aligned.m16n8k8.row.col.f32.tf32.tf32.f32 " \
        "{%0,%1,%2,%3}, {%4,%5,%6,%7}, {%8,%9}, {%0,%1,%2,%3};" \
        : "+f"((c)[0]), "+f"((c)[1]), "+f"((c)[2]), "+f"((c)[3]) \
        : "r"((a)[0]), "r"((a)[1]), "r"((a)[2]), "r"((a)[3]), \
          "r"((b)[0]), "r"((b)[1]))

// ---------------- weight rounding prep ---------------------------------------
__global__ void round_w(const float* __restrict__ wq, const float* __restrict__ wk,
                        const float* __restrict__ wv, const float* __restrict__ wo) {
    int i = blockIdx.x * 256 + threadIdx.x;       // 262144 per matrix
    g_wr[i]              = f2tff(wq[i]);
    g_wr[262144 + i]     = f2tff(wk[i]);
    g_wr[2 * 262144 + i] = f2tff(wv[i]);
    g_wr[3 * 262144 + i] = f2tff(wo[i]);
}

// ---------------- LayerNorm (rounds output to tf32) --------------------------
__global__ void ln_kernel(const float* __restrict__ x,
                          const float* __restrict__ gamma,
                          const float* __restrict__ beta) {
    int row = blockIdx.x;
    int tid = threadIdx.x;            // 256 threads
    const float* xr = x + (size_t)row * D_MODEL;
    float v0 = xr[tid];
    float v1 = xr[tid + 256];
    float s  = v0 + v1;
    float sq = v0 * v0 + v1 * v1;
    #pragma unroll
    for (int o = 16; o > 0; o >>= 1) {
        s  += __shfl_xor_sync(0xffffffffu, s,  o);
        sq += __shfl_xor_sync(0xffffffffu, sq, o);
    }
    __shared__ float ss[8], ssq[8];
    __shared__ float s_mu, s_rstd;
    int w = tid >> 5, l = tid & 31;
    if (l == 0) { ss[w] = s; ssq[w] = sq; }
    __syncthreads();
    if (tid == 0) {
        float S = 0.f, SQ = 0.f;
        #pragma unroll
        for (int i = 0; i < 8; i++) { S += ss[i]; SQ += ssq[i]; }
        float mu = S * (1.0f / D_MODEL);
        float var = SQ * (1.0f / D_MODEL) - mu * mu;
        s_mu = mu;
        s_rstd = rsqrtf(var + LN_EPS);
    }
    __syncthreads();
    float mu = s_mu, rs = s_rstd;
    float* out = g_normed + (size_t)row * D_MODEL;
    out[tid]       = f2tff((v0 - mu) * rs * gamma[tid]       + beta[tid]);
    out[tid + 256] = f2tff((v1 - mu) * rs * gamma[tid + 256] + beta[tid + 256]);
}

// ---------------- shared 128x128x512 tf32 mainloop ---------------------------
// 256 threads, 8 warps (2m x 4n), warp tile 64x32, BK=32, double-buffered.
// smem: A [2][128][32] swizzled @0 (32KB), B same @32768. Total 65536.
#define GEMM_SMEM 65536

__device__ __forceinline__ void gemm_mainloop(
    const float* __restrict__ A, const float* __restrict__ B,
    int m0, int n0, char* smem, float acc[4][4][4])
{
    uint32_t sA = smem_u32(smem), sB = sA + 32768;
    int tid = threadIdx.x, wid = tid >> 5, lane = tid & 31;
    int wm = (wid >> 2) * 64, wn = (wid & 3) * 32;

    #pragma unroll
    for (int i = 0; i < 4; i++) {
        int id = tid + i * 256, r = id >> 3, c = id & 7;
        uint32_t off = (uint32_t)((r * 8 + (c ^ (r & 7))) * 16);
        CP16(sA + off, A + (size_t)(m0 + r) * 512 + c * 4);
        CP16(sB + off, B + (size_t)(n0 + r) * 512 + c * 4);
    }
    CP_COMMIT();

    for (int itk = 0; itk < 16; itk++) {
        int buf = itk & 1;
        if (itk < 15) {
            int k0 = (itk + 1) * 32, nb = (itk + 1) & 1;
            #pragma unroll
            for (int i = 0; i < 4; i++) {
                int id = tid + i * 256, r = id >> 3, c = id & 7;
                uint32_t off = (uint32_t)(nb * 16384 + (r * 8 + (c ^ (r & 7))) * 16);
                CP16(sA + off, A + (size_t)(m0 + r) * 512 + k0 + c * 4);
                CP16(sB + off, B + (size_t)(n0 + r) * 512 + k0 + c * 4);
            }
            CP_COMMIT();
            CP_WAIT1();
        } else {
            CP_WAIT0();
        }
        __syncthreads();

        uint32_t ab = sA + buf * 16384, bb = sB + buf * 16384;
        #pragma unroll
        for (int ks = 0; ks < 4; ks++) {
            uint32_t af[4][4];
            #pragma unroll
            for (int mi = 0; mi < 4; mi++) {
                int r = wm + mi * 16 + (lane & 15);
                int c = 2 * ks + (lane >> 4);
                LDSM4(af[mi][0], af[mi][1], af[mi][2], af[mi][3],
                      ab + (r * 8 + (c ^ (r & 7))) * 16);
            }
            uint32_t bf[4][2];
            #pragma unroll
            for (int nj2 = 0; nj2 < 2; nj2++) {
                int r = wn + nj2 * 16 + (lane & 7) + ((lane >> 4) << 3);
                int c = 2 * ks + ((lane >> 3) & 1);
                uint32_t t0, t1, t2, t3;
                LDSM4(t0, t1, t2, t3, bb + (r * 8 + (c ^ (r & 7))) * 16);
                bf[nj2 * 2][0] = t0; bf[nj2 * 2][1] = t1;
                bf[nj2 * 2 + 1][0] = t2; bf[nj2 * 2 + 1][1] = t3;
            }
            #pragma unroll
            for (int mi = 0; mi < 4; mi++)
                #pragma unroll
                for (int nj = 0; nj < 4; nj++)
                    MMA_TF32(acc[mi][nj], af[mi], bf[nj]);
        }
        __syncthreads();
    }
}

// ---------------- QKV projection (+bias, +PE on K, head scatter) -------------
__global__ __launch_bounds__(256) void qkv_tc(
    const float* __restrict__ bq, const float* __restrict__ bk,
    const float* __restrict__ bv)
{
    extern __shared__ char smem[];
    int tid = threadIdx.x, wid = tid >> 5, lane = tid & 31;
    int m0 = blockIdx.x * 128;
    int ng = blockIdx.y * 128;
    int wsel = ng >> 9, n0 = ng & 511;

    float acc[4][4][4];
    #pragma unroll
    for (int a = 0; a < 4; a++)
        #pragma unroll
        for (int b = 0; b < 4; b++)
            #pragma unroll
            for (int c = 0; c < 4; c++) acc[a][b][c] = 0.f;

    gemm_mainloop(g_normed, g_wr + (size_t)wsel * 262144, m0, n0, smem, acc);

    const float* bias = (wsel == 0) ? bq : (wsel == 1) ? bk : bv;
    int wm = (wid >> 2) * 64, wn = (wid & 3) * 32;
    #pragma unroll
    for (int mi = 0; mi < 4; mi++) {
        #pragma unroll
        for (int rr = 0; rr < 2; rr++) {
            int m = m0 + wm + mi * 16 + (lane >> 2) + rr * 8;
            int b = m >> 11, t = m & (SEQ - 1);
            #pragma unroll
            for (int nj = 0; nj < 4; nj++) {
                #pragma unroll
                for (int cc = 0; cc < 2; cc++) {
                    int n = n0 + wn + nj * 8 + (lane & 3) * 2 + cc;
                    float v = acc[mi][nj][rr * 2 + cc] + bias[n];
                    int h = n >> 6, d = n & 63;
                    size_t bh = (size_t)(b * N_HEADS + h);
                    if (wsel == 0) {
                        g_q[(bh * SEQ + t) * DK + d] = f2tff(v);
                    } else if (wsel == 1) {
                        float f = expf(-PE_C * (float)(d & ~1));
                        float ang = (float)t * f;
                        v += (d & 1) ? cosf(ang) : sinf(ang);
                        g_k[(bh * SEQ + t) * DK + d] = f2tff(v);
                    } else {
                        g_vt[(bh * DK + d) * SEQ + t] = f2tff(v);
                    }
                }
            }
        }
    }
}

// ---------------- output projection ------------------------------------------
__global__ __launch_bounds__(256) void out_tc(const float* __restrict__ bo,
                                              float* __restrict__ out)
{
    extern __shared__ char smem[];
    int tid = threadIdx.x, wid = tid >> 5, lane = tid & 31;
    int m0 = blockIdx.x * 128;
    int n0 = blockIdx.y * 128;

    float acc[4][4][4];
    #pragma unroll
    for (int a = 0; a < 4; a++)
        #pragma unroll
        for (int b = 0; b < 4; b++)
            #pragma unroll
            for (int c = 0; c < 4; c++) acc[a][b][c] = 0.f;

    gemm_mainloop(g_ctx, g_wr + 3 * 262144, m0, n0, smem, acc);

    int wm = (wid >> 2) * 64, wn = (wid & 3) * 32;
    #pragma unroll
    for (int mi = 0; mi < 4; mi++) {
        #pragma unroll
        for (int rr = 0; rr < 2; rr++) {
            int m = m0 + wm + mi * 16 + (lane >> 2) + rr * 8;
            #pragma unroll
            for (int nj = 0; nj < 4; nj++) {
                int n = n0 + wn + nj * 8 + (lane & 3) * 2;
                float2 v;
                v.x = acc[mi][nj][rr * 2]     + bo[n];
                v.y = acc[mi][nj][rr * 2 + 1] + bo[n + 1];
                *(float2*)(out + (size_t)m * 512 + n) = v;
            }
        }
    }
}

// ---------------- flash attention (tf32 mma.sync) ----------------------------
// CTA: 128 q-rows, 8 warps each owning m16. K/V tile = 64, double buffered.
// smem: Qs[128][64]@0 32KB, Ks[2][64][64]@32768 32KB, Vts[2][64][64]@65536 32KB,
//       Ps[128][64]@98304 32KB. Total 131072. All f32, XOR-swizzled 16B chunks.
#define ATTN_SMEM 131072

__global__ __launch_bounds__(256) void attn_tc() {
    extern __shared__ char smem[];
    uint32_t sQ = smem_u32(smem);
    uint32_t sK = sQ + 32768;
    uint32_t sV = sQ + 65536;
    uint32_t sP = sQ + 98304;
    int tid = threadIdx.x, wid = tid >> 5, lane = tid & 31;
    int bh = blockIdx.z * N_HEADS + blockIdx.y;
    int q0 = blockIdx.x * 128;
    const float* Qb  = g_q  + (size_t)bh * SEQ * DK;
    const float* Kb  = g_k  + (size_t)bh * SEQ * DK;
    const float* Vtb = g_vt + (size_t)bh * DK * SEQ;

    // stage Q [128 x 64] : 2048 chunks of 16B
    #pragma unroll
    for (int i = 0; i < 8; i++) {
        int id = tid + i * 256, r = id >> 4, c = id & 15;
        CP16(sQ + (r * 16 + (c ^ (r & 7))) * 16, Qb + (size_t)(q0 + r) * DK + c * 4);
    }
    CP_COMMIT();
    // stage K/V tile 0
    #pragma unroll
    for (int i = 0; i < 4; i++) {
        int id = tid + i * 256, r = id >> 4, c = id & 15;
        uint32_t off = (r * 16 + (c ^ (r & 7))) * 16;
        CP16(sK + off, Kb + (size_t)r * DK + c * 4);
        CP16(sV + off, Vtb + (size_t)r * SEQ + c * 4);
    }
    CP_COMMIT();

    float accO[8][4];
    #pragma unroll
    for (int nj = 0; nj < 8; nj++)
        #pragma unroll
        for (int k = 0; k < 4; k++) accO[nj][k] = 0.f;
    float mrun0 = -1e30f, mrun1 = -1e30f, l0 = 0.f, l1 = 0.f;

    for (int it = 0; it < 32; it++) {
        int buf = it & 1;
        if (it < 31) {
            int s0 = (it + 1) * 64, nb = (it + 1) & 1;
            #pragma unroll
            for (int i = 0; i < 4; i++) {
                int id = tid + i * 256, r = id >> 4, c = id & 15;
                uint32_t off = nb * 16384 + (r * 16 + (c ^ (r & 7))) * 16;
                CP16(sK + off, Kb + (size_t)(s0 + r) * DK + c * 4);
                CP16(sV + off, Vtb + (size_t)r * SEQ + s0 + c * 4);
            }
            CP_COMMIT();
            CP_WAIT1();
        } else {
            CP_WAIT0();
        }
        __syncthreads();

        uint32_t kb = sK + buf * 16384, vb = sV + buf * 16384;

        // ---- S = Q @ K^T : per-warp m16 x n64, k=64 (8 ksteps) ----
        float s[8][4];
        #pragma unroll
        for (int nj = 0; nj < 8; nj++)
            #pragma unroll
            for (int k = 0; k < 4; k++) s[nj][k] = 0.f;
        #pragma unroll
        for (int ks = 0; ks < 8; ks++) {
            uint32_t af[4];
            {
                int r = wid * 16 + (lane & 15);
                int c = 2 * ks + (lane >> 4);
                LDSM4(af[0], af[1], af[2], af[3], sQ + (r * 16 + (c ^ (r & 7))) * 16);
            }
            #pragma unroll
            for (int nj2 = 0; nj2 < 4; nj2++) {
                int r = nj2 * 16 + (lane & 7) + ((lane >> 4) << 3);
                int c = 2 * ks + ((lane >> 3) & 1);
                uint32_t t0, t1, t2, t3;
                LDSM4(t0, t1, t2, t3, kb + (r * 16 + (c ^ (r & 7))) * 16);
                uint32_t b0[2] = {t0, t1}, b1[2] = {t2, t3};
                MMA_TF32(s[nj2 * 2], af, b0);
                MMA_TF32(s[nj2 * 2 + 1], af, b1);
            }
        }

        // ---- online softmax (rows g and g+8 per lane) ----
        #pragma unroll
        for (int nj = 0; nj < 8; nj++)
            #pragma unroll
            for (int k = 0; k < 4; k++) s[nj][k] *= 0.125f;
        float ml0 = -1e30f, ml1 = -1e30f;
        #pragma unroll
        for (int nj = 0; nj < 8; nj++) {
            ml0 = fmaxf(ml0, fmaxf(s[nj][0], s[nj][1]));
            ml1 = fmaxf(ml1, fmaxf(s[nj][2], s[nj][3]));
        }
        ml0 = fmaxf(ml0, __shfl_xor_sync(0xffffffffu, ml0, 1));
        ml0 = fmaxf(ml0, __shfl_xor_sync(0xffffffffu, ml0, 2));
        ml1 = fmaxf(ml1, __shfl_xor_sync(0xffffffffu, ml1, 1));
        ml1 = fmaxf(ml1, __shfl_xor_sync(0xffffffffu, ml1, 2));
        float mn0 = fmaxf(mrun0, ml0), mn1 = fmaxf(mrun1, ml1);
        float al0 = __expf(mrun0 - mn0), al1 = __expf(mrun1 - mn1);
        float rs0 = 0.f, rs1 = 0.f;
        #pragma unroll
        for (int nj = 0; nj < 8; nj++) {
            s[nj][0] = __expf(s[nj][0] - mn0);
            s[nj][1] = __expf(s[nj][1] - mn0);
            s[nj][2] = __expf(s[nj][2] - mn1);
            s[nj][3] = __expf(s[nj][3] - mn1);
            rs0 += s[nj][0] + s[nj][1];
            rs1 += s[nj][2] + s[nj][3];
        }
        rs0 += __shfl_xor_sync(0xffffffffu, rs0, 1);
        rs0 += __shfl_xor_sync(0xffffffffu, rs0, 2);
        rs1 += __shfl_xor_sync(0xffffffffu, rs1, 1);
        rs1 += __shfl_xor_sync(0xffffffffu, rs1, 2);
        l0 = l0 * al0 + rs0;  l1 = l1 * al1 + rs1;
        mrun0 = mn0;          mrun1 = mn1;
        #pragma unroll
        for (int nj = 0; nj < 8; nj++) {
            accO[nj][0] *= al0; accO[nj][1] *= al0;
            accO[nj][2] *= al1; accO[nj][3] *= al1;
        }

        // ---- store P (tf32-rounded) to smem in A-operand layout ----
        {
            int r0 = wid * 16 + (lane >> 2), r1 = r0 + 8;
            int off8 = (lane & 1) * 8;
            #pragma unroll
            for (int nj = 0; nj < 8; nj++) {
                int col = nj * 8 + (lane & 3) * 2;
                int ch = col >> 2;
                STS64(sP + (r0 * 16 + (ch ^ (r0 & 7))) * 16 + off8,
                      f2tf(s[nj][0]), f2tf(s[nj][1]));
                STS64(sP + (r1 * 16 + (ch ^ (r1 & 7))) * 16 + off8,
                      f2tf(s[nj][2]), f2tf(s[nj][3]));
            }
        }
        __syncwarp();

        // ---- O += P @ V : per-warp m16 x n64(d), k=64(s) ----
        #pragma unroll
        for (int ks = 0; ks < 8; ks++) {
            uint32_t af[4];
            {
                int r = wid * 16 + (lane & 15);
                int c = 2 * ks + (lane >> 4);
                LDSM4(af[0], af[1], af[2], af[3], sP + (r * 16 + (c ^ (r & 7))) * 16);
            }
            #pragma unroll
            for (int nj2 = 0; nj2 < 4; nj2++) {
                int r = nj2 * 16 + (lane & 7) + ((lane >> 4) << 3);
                int c = 2 * ks + ((lane >> 3) & 1);
                uint32_t t0, t1, t2, t3;
                LDSM4(t0, t1, t2, t3, vb + (r * 16 + (c ^ (r & 7))) * 16);
                uint32_t b0[2] = {t0, t1}, b1[2] = {t2, t3};
                MMA_TF32(accO[nj2 * 2], af, b0);
                MMA_TF32(accO[nj2 * 2 + 1], af, b1);
            }
        }
        __syncthreads();
    }

    // ---- epilogue: normalize, round, write to g_ctx ----
    float inv0 = 1.0f / l0, inv1 = 1.0f / l1;
    int t0 = q0 + wid * 16 + (lane >> 2), t1 = t0 + 8;
    float* dst = g_ctx + (size_t)blockIdx.z * SEQ * D_MODEL + (size_t)blockIdx.y * DK;
    #pragma unroll
    for (int nj = 0; nj < 8; nj++) {
        int col = nj * 8 + (lane & 3) * 2;
        float2 v0, v1;
        v0.x = f2tff(accO[nj][0] * inv0); v0.y = f2tff(accO[nj][1] * inv0);
        v1.x = f2tff(accO[nj][2] * inv1); v1.y = f2tff(accO[nj][3] * inv1);
        *(float2*)(dst + (size_t)t0 * D_MODEL + col) = v0;
        *(float2*)(dst + (size_t)t1 * D_MODEL + col) = v1;
    }
}

// ---------------- launch -----------------------------------------------------
extern "C" void kernel_launch(void* const* d_in, const int* in_sizes, int n_in,
                              void* d_out, int out_size) {
    const float* x    = (const float*)d_in[0];
    const float* ln_g = (const float*)d_in[1];
    const float* ln_b = (const float*)d_in[2];
    const float* wq   = (const float*)d_in[3];
    const float* bq   = (const float*)d_in[4];
    const float* wk   = (const float*)d_in[5];
    const float* bk   = (const float*)d_in[6];
    const float* wv   = (const float*)d_in[7];
    const float* bv   = (const float*)d_in[8];
    const float* wo   = (const float*)d_in[9];
    const float* bo   = (const float*)d_in[10];

    cudaFuncSetAttribute(qkv_tc,  cudaFuncAttributeMaxDynamicSharedMemorySize, GEMM_SMEM);
    cudaFuncSetAttribute(out_tc,  cudaFuncAttributeMaxDynamicSharedMemorySize, GEMM_SMEM);
    cudaFuncSetAttribute(attn_tc, cudaFuncAttributeMaxDynamicSharedMemorySize, ATTN_SMEM);

    round_w<<<1024, 256>>>(wq, wk, wv, wo);
    ln_kernel<<<BT, 256>>>(x, ln_g, ln_b);
    qkv_tc<<<dim3(64, 12), 256, GEMM_SMEM>>>(bq, bk, bv);
    attn_tc<<<dim3(16, 8, 4), 256, ATTN_SMEM>>>();
    out_tc<<<dim3(64, 4), 256, GEMM_SMEM>>>(bo, (float*)d_out);
}